// round 8
// baseline (speedup 1.0000x reference)
#include <cuda_runtime.h>

#define NR 8192
#define NT 8192
#define RB 64
#define CB 64
#define NF (NT / 4)            // 2048 float4 per row
#define NWORK (RB * 8 * 4)     // 2048 worker CTAs
#define NCTA (NWORK + 1)       // + boundary publisher

// Device scratch. g_B zero-init; the finishing CTA re-zeros it and resets
// g_ctr, so every launch (and every graph replay) starts from the same state.
__device__ float    g_B[RB * CB];
__device__ int      g_rcum[RB + 1];
__device__ int      g_ccum[CB + 1];
__device__ unsigned g_ctr = 0;

// Warp-collective lower bound: first i with ids[i] >= b (ids sorted). 3 ballots.
__device__ __forceinline__ int warp_lb(const int* __restrict__ ids, int b, int lane) {
    int start = 0;
    {
        bool p = ids[lane << 8] >= b;
        unsigned m = __ballot_sync(0xFFFFFFFFu, p);
        int cf = (m == 0u) ? 32 : (__ffs(m) - 1);
        start = (cf == 0) ? 0 : (((cf - 1) << 8) + 1);
    }
    {
        int i = start + (lane << 3);
        bool p = (i >= NR) ? true : (ids[i] >= b);
        unsigned m = __ballot_sync(0xFFFFFFFFu, p);
        int cf = (m == 0u) ? 32 : (__ffs(m) - 1);
        if (cf > 0) start += ((cf - 1) << 3) + 1;
    }
    {
        int i = start + lane;
        bool p = (i >= NR) ? true : (ids[i] >= b);
        unsigned m = __ballot_sync(0xFFFFFFFFu, p);
        int cf = (m == 0u) ? 32 : (__ffs(m) - 1);
        return start + cf;
    }
}

// ---------------------------------------------------------------------------
// Single fused kernel.
// Worker CTA = (rb, tile, quarter): logic-free streaming sum of its ~32 rows
// over a 1024-col panel, then an epilogue segment-reduce of the panel sums
// into g_B via smem. CTA NWORK publishes rcum/ccum. The LAST CTA to finish
// (threadfence + atomic counter) computes the 64x64 block-mean MLP outputs
// and restores all scratch state.
// ---------------------------------------------------------------------------
__global__ __launch_bounds__(256) void k_fused(const float* __restrict__ X,
                                               const int* __restrict__ row_ids,
                                               const int* __restrict__ col_ids,
                                               const float* __restrict__ W1, const float* __restrict__ b1,
                                               const float* __restrict__ W2, const float* __restrict__ b2,
                                               const float* __restrict__ W3, const float* __restrict__ b3,
                                               float* __restrict__ out, int out_size) {
    __shared__ float4 sbuf[256];       // staged panel sums (4 KB)
    __shared__ float  wsum[CB];
    __shared__ int    scum[CB + 1];
    __shared__ int    sb[2];
    __shared__ unsigned s_rank;

    const int bx   = blockIdx.x;
    const int tid  = threadIdx.x;
    const int lane = tid & 31;
    const int w    = tid >> 5;

    if (bx == NWORK) {
        // ---- boundary publisher ----
        for (int i = tid; i < NR; i += 256) {
            int cur  = row_ids[i];
            int prev = i ? row_ids[i - 1] : -1;
            for (int b = prev; b < cur; b++) g_rcum[b + 1] = i;
        }
        for (int i = tid; i < NT; i += 256) {
            int cur  = col_ids[i];
            int prev = i ? col_ids[i - 1] : -1;
            for (int b = prev; b < cur; b++) g_ccum[b + 1] = i;
        }
        if (tid == 0) { g_rcum[0] = 0; g_rcum[RB] = NR; g_ccum[0] = 0; g_ccum[CB] = NT; }
    } else {
        // ---- worker ----
        const int rb      = bx >> 5;
        const int sub     = bx & 31;
        const int tile    = sub >> 2;
        const int quarter = sub & 3;

        if (w == 0) { int v = warp_lb(row_ids, rb,     lane); if (lane == 0) sb[0] = v; }
        if (w == 1) { int v = warp_lb(row_ids, rb + 1, lane); if (lane == 0) sb[1] = v; }
        if (tid < CB) wsum[tid] = 0.0f;
        __syncthreads();
        const int r0rb = sb[0], nrb = sb[1] - sb[0];
        const int r0 = r0rb + (nrb * quarter) / 4;
        const int r1 = r0rb + (nrb * (quarter + 1)) / 4;

        // ---- hot loop: logic-free streaming column sums ----
        const int fcol  = (tile << 8) + tid;             // float4 column
        const float4* p = (const float4*)X + (size_t)r0 * NF + fcol;
        float4 a0 = make_float4(0.f, 0.f, 0.f, 0.f);
        float4 a1 = make_float4(0.f, 0.f, 0.f, 0.f);
        int r = r0;
        for (; r + 8 <= r1; r += 8) {
            float4 q0 = p[0 * NF], q1 = p[1 * NF], q2 = p[2 * NF], q3 = p[3 * NF];
            float4 q4 = p[4 * NF], q5 = p[5 * NF], q6 = p[6 * NF], q7 = p[7 * NF];
            a0.x += q0.x; a0.y += q0.y; a0.z += q0.z; a0.w += q0.w;
            a1.x += q4.x; a1.y += q4.y; a1.z += q4.z; a1.w += q4.w;
            a0.x += q1.x; a0.y += q1.y; a0.z += q1.z; a0.w += q1.w;
            a1.x += q5.x; a1.y += q5.y; a1.z += q5.z; a1.w += q5.w;
            a0.x += q2.x; a0.y += q2.y; a0.z += q2.z; a0.w += q2.w;
            a1.x += q6.x; a1.y += q6.y; a1.z += q6.z; a1.w += q6.w;
            a0.x += q3.x; a0.y += q3.y; a0.z += q3.z; a0.w += q3.w;
            a1.x += q7.x; a1.y += q7.y; a1.z += q7.z; a1.w += q7.w;
            p += 8 * NF;
        }
        for (; r < r1; r++) {
            float4 q = p[0];
            a0.x += q.x; a0.y += q.y; a0.z += q.z; a0.w += q.w;
            p += NF;
        }
        a0.x += a1.x; a0.y += a1.y; a0.z += a1.z; a0.w += a1.w;
        sbuf[tid] = a0;

        // col-block boundaries (L2-hot by now)
        for (int i = tid; i < NT; i += 256) {
            int cur  = col_ids[i];
            int prev = i ? col_ids[i - 1] : -1;
            for (int b = prev; b < cur; b++) scum[b + 1] = i;
        }
        if (tid == 0) { scum[0] = 0; scum[CB] = NT; }
        __syncthreads();

        // ---- epilogue: segment-reduce the 1024-col panel (once per CTA) ----
        if (tid < 64) {
            const int g0 = (tile << 10) + (tid << 4);    // 16 contiguous cols
            int lo = 0, hi = CB;
            while (lo < hi) {
                int mid = (lo + hi + 1) >> 1;
                if (scum[mid] <= g0) lo = mid; else hi = mid - 1;
            }
            int cb = lo;
            int nb = scum[cb + 1];
            float acc = 0.0f;
#pragma unroll
            for (int j = 0; j < 4; j++) {
                float4 q = sbuf[(tid << 2) + j];
                float e[4] = {q.x, q.y, q.z, q.w};
#pragma unroll
                for (int k = 0; k < 4; k++) {
                    int c = g0 + (j << 2) + k;
                    while (c >= nb) {
                        if (acc != 0.0f) atomicAdd(&wsum[cb], acc);
                        acc = 0.0f;
                        cb++;
                        nb = scum[cb + 1];
                    }
                    acc += e[k];
                }
            }
            if (acc != 0.0f) atomicAdd(&wsum[cb], acc);
        }
        __syncthreads();
        if (tid < CB && wsum[tid] != 0.0f)
            atomicAdd(&g_B[rb * CB + tid], wsum[tid]);
    }

    // ---- completion: last CTA finishes the job ----
    __threadfence();
    __syncthreads();
    if (tid == 0) s_rank = atomicAdd(&g_ctr, 1u);
    __syncthreads();
    if (s_rank != NCTA - 1) return;

    // (all g_B / g_rcum / g_ccum writes are visible: fence + atomic chain)
    if (tid < CB * 2) {
        const int rb2 = tid >> 6;            // process 2 row-blocks per pass
        const int cb  = tid & 63;
        for (int rb = rb2; rb < RB; rb += 2) {
            const float s      = g_B[rb * CB + cb];
            const float rcount = (float)(g_rcum[rb + 1] - g_rcum[rb]);
            const float ccount = (float)(g_ccum[cb + 1] - g_ccum[cb]);
            const float x      = s / (rcount * ccount);

            float h1[3], h2[3];
#pragma unroll
            for (int k = 0; k < 3; k++) h1[k] = fmaxf(x * W1[k] + b1[k], 0.0f);
#pragma unroll
            for (int j = 0; j < 3; j++) {
                float z = b2[j];
#pragma unroll
                for (int k = 0; k < 3; k++) z += h1[k] * W2[k * 3 + j];
                h2[j] = fmaxf(z, 0.0f);
            }
            float z = b3[0];
#pragma unroll
            for (int j = 0; j < 3; j++) z += h2[j] * W3[j];

            out[rb * CB + cb] = 1.0f / (1.0f + expf(-z));
            g_B[rb * CB + cb] = 0.0f;        // restore invariant
        }
    }

    if (out_size >= RB * CB + 2 * (RB + 1) && tid <= RB) {
        out[RB * CB + tid]            = (float)g_rcum[tid];
        out[RB * CB + (RB + 1) + tid] = (float)g_ccum[tid];
    }
    __syncthreads();
    if (tid == 0) g_ctr = 0;                 // reset for next replay
}

// ---------------------------------------------------------------------------
extern "C" void kernel_launch(void* const* d_in, const int* in_sizes, int n_in,
                              void* d_out, int out_size) {
    const float* X       = (const float*)d_in[0];
    const int*   row_ids = (const int*)d_in[1];
    const int*   col_ids = (const int*)d_in[2];
    const float* W1      = (const float*)d_in[3];
    const float* b1      = (const float*)d_in[4];
    const float* W2      = (const float*)d_in[5];
    const float* b2      = (const float*)d_in[6];
    const float* W3      = (const float*)d_in[7];
    const float* b3      = (const float*)d_in[8];
    float* out = (float*)d_out;

    k_fused<<<NCTA, 256>>>(X, row_ids, col_ids, W1, b1, W2, b2, W3, b3, out, out_size);
}

// round 13
// speedup vs baseline: 1.6824x; 1.6824x over previous
#include <cuda_runtime.h>

#define NR 8192
#define NT 8192
#define RB 64
#define CB 64
#define NF (NT / 4)          // 2048 float4 per row
#define NWORK (RB * 8 * 2)   // 1024 worker CTAs (rb x 8 tiles x 2 halves)
#define GRIDT (RB * 8)       // 512 tail CTAs (rb x 8 tiles)

// Device scratch. g_B zero-init; last tail CTA re-zeros it + resets g_ctr,
// so every launch / graph replay starts from identical state.
__device__ float4   g_S1[2][RB * NF];   // two half-slabs, 4 MB total
__device__ float    g_B[RB * CB];
__device__ int      g_rcum[RB + 1];
__device__ int      g_ccum[CB + 1];
__device__ unsigned g_ctr = 0;

// Warp-collective lower bound: first i with ids[i] >= b (ids sorted). 3 ballots.
__device__ __forceinline__ int warp_lb(const int* __restrict__ ids, int b, int lane) {
    int start = 0;
    {
        bool p = ids[lane << 8] >= b;
        unsigned m = __ballot_sync(0xFFFFFFFFu, p);
        int cf = (m == 0u) ? 32 : (__ffs(m) - 1);
        start = (cf == 0) ? 0 : (((cf - 1) << 8) + 1);
    }
    {
        int i = start + (lane << 3);
        bool p = (i >= NR) ? true : (ids[i] >= b);
        unsigned m = __ballot_sync(0xFFFFFFFFu, p);
        int cf = (m == 0u) ? 32 : (__ffs(m) - 1);
        if (cf > 0) start += ((cf - 1) << 3) + 1;
    }
    {
        int i = start + lane;
        bool p = (i >= NR) ? true : (ids[i] >= b);
        unsigned m = __ballot_sync(0xFFFFFFFFu, p);
        int cf = (m == 0u) ? 32 : (__ffs(m) - 1);
        return start + cf;
    }
}

__device__ __forceinline__ float4 ldcs4(const float4* p) {
    return __ldcs(p);    // evict-first streaming load
}

// ---------------------------------------------------------------------------
// k_main: the 256 MB pass (R6-proven structure).
// Worker CTA = (rb, tile, half): logic-free streaming column sums of its
// ~64 rows over a 1024-col panel; plain float4 stores to its own slab.
// CTAs 1024/1025 publish rcum/ccum (overlapped, workers never touch ids
// beyond two warp_lb searches).
// ---------------------------------------------------------------------------
__global__ __launch_bounds__(256) void k_main(const float* __restrict__ X,
                                              const int* __restrict__ row_ids,
                                              const int* __restrict__ col_ids) {
    const int bx  = blockIdx.x;
    const int tid = threadIdx.x;

    if (bx >= NWORK) {                   // boundary publishers
        if (bx == NWORK) {
            for (int i = tid; i < NR; i += 256) {
                int cur  = row_ids[i];
                int prev = i ? row_ids[i - 1] : -1;
                for (int b = prev; b < cur; b++) g_rcum[b + 1] = i;
            }
            if (tid == 0) { g_rcum[0] = 0; g_rcum[RB] = NR; }
        } else {
            for (int i = tid; i < NT; i += 256) {
                int cur  = col_ids[i];
                int prev = i ? col_ids[i - 1] : -1;
                for (int b = prev; b < cur; b++) g_ccum[b + 1] = i;
            }
            if (tid == 0) { g_ccum[0] = 0; g_ccum[CB] = NT; }
        }
        return;
    }

    const int rb   = bx >> 4;
    const int sub  = bx & 15;
    const int tile = sub >> 1;
    const int half = sub & 1;
    const int lane = tid & 31;
    const int w    = tid >> 5;

    __shared__ int sb[2];
    if (w == 0) { int v = warp_lb(row_ids, rb,     lane); if (lane == 0) sb[0] = v; }
    if (w == 1) { int v = warp_lb(row_ids, rb + 1, lane); if (lane == 0) sb[1] = v; }
    __syncthreads();
    const int r0rb = sb[0], r1rb = sb[1];
    const int mid  = r0rb + ((r1rb - r0rb) >> 1);
    const int r0   = half ? mid : r0rb;
    const int r1   = half ? r1rb : mid;

    const int fcol  = (tile << 8) + tid;                 // float4 column
    const float4* p = (const float4*)X + (size_t)r0 * NF + fcol;

    float4 a0 = make_float4(0.f, 0.f, 0.f, 0.f);
    float4 a1 = make_float4(0.f, 0.f, 0.f, 0.f);
    int r = r0;
    for (; r + 8 <= r1; r += 8) {                        // 8 LDG.128 in flight
        float4 q0 = ldcs4(p + 0 * NF), q1 = ldcs4(p + 1 * NF);
        float4 q2 = ldcs4(p + 2 * NF), q3 = ldcs4(p + 3 * NF);
        float4 q4 = ldcs4(p + 4 * NF), q5 = ldcs4(p + 5 * NF);
        float4 q6 = ldcs4(p + 6 * NF), q7 = ldcs4(p + 7 * NF);
        a0.x += q0.x; a0.y += q0.y; a0.z += q0.z; a0.w += q0.w;
        a1.x += q4.x; a1.y += q4.y; a1.z += q4.z; a1.w += q4.w;
        a0.x += q1.x; a0.y += q1.y; a0.z += q1.z; a0.w += q1.w;
        a1.x += q5.x; a1.y += q5.y; a1.z += q5.z; a1.w += q5.w;
        a0.x += q2.x; a0.y += q2.y; a0.z += q2.z; a0.w += q2.w;
        a1.x += q6.x; a1.y += q6.y; a1.z += q6.z; a1.w += q6.w;
        a0.x += q3.x; a0.y += q3.y; a0.z += q3.z; a0.w += q3.w;
        a1.x += q7.x; a1.y += q7.y; a1.z += q7.z; a1.w += q7.w;
        p += 8 * NF;
    }
    for (; r < r1; r++) {
        float4 q = ldcs4(p);
        a0.x += q.x; a0.y += q.y; a0.z += q.z; a0.w += q.w;
        p += NF;
    }
    a0.x += a1.x; a0.y += a1.y; a0.z += a1.z; a0.w += a1.w;

    g_S1[half][rb * NF + fcol] = a0;                     // plain store, no race
}

// ---------------------------------------------------------------------------
// k_tail: grid 512 = (rb, tile). Each CTA combines its 8 KB panel from the
// two slabs and segment-reduces it into g_B (scum loaded from g_ccum — no
// scans, no searches). The LAST CTA (fence + counter) runs the 64x64 MLP,
// writes the cumsum tails, re-zeros g_B, resets the counter.
// ---------------------------------------------------------------------------
__global__ __launch_bounds__(256) void k_tail(const float* __restrict__ W1, const float* __restrict__ b1,
                                              const float* __restrict__ W2, const float* __restrict__ b2,
                                              const float* __restrict__ W3, const float* __restrict__ b3,
                                              float* __restrict__ out, int out_size) {
    __shared__ float4 sbuf[256];
    __shared__ float  wsum[CB];
    __shared__ int    scum[CB + 1];
    __shared__ unsigned s_rank;

    const int tid  = threadIdx.x;
    const int rb   = blockIdx.x >> 3;
    const int tile = blockIdx.x & 7;

    if (tid <= CB) scum[tid] = g_ccum[tid];
    if (tid < CB)  wsum[tid] = 0.0f;

    const int idx = rb * NF + (tile << 8) + tid;
    float4 qa = g_S1[0][idx], qb = g_S1[1][idx];
    qa.x += qb.x; qa.y += qb.y; qa.z += qb.z; qa.w += qb.w;
    sbuf[tid] = qa;
    __syncthreads();

    if (tid < 64) {
        const int g0 = (tile << 10) + (tid << 4);        // 16 contiguous cols
        int lo = 0, hi = CB;
        while (lo < hi) {
            int mid = (lo + hi + 1) >> 1;
            if (scum[mid] <= g0) lo = mid; else hi = mid - 1;
        }
        int cb = lo;
        int nb = scum[cb + 1];
        float acc = 0.0f;
#pragma unroll
        for (int j = 0; j < 4; j++) {
            float4 q = sbuf[(tid << 2) + j];
            float e[4] = {q.x, q.y, q.z, q.w};
#pragma unroll
            for (int k = 0; k < 4; k++) {
                int c = g0 + (j << 2) + k;
                while (c >= nb) {
                    if (acc != 0.0f) atomicAdd(&wsum[cb], acc);
                    acc = 0.0f;
                    cb++;
                    nb = scum[cb + 1];
                }
                acc += e[k];
            }
        }
        if (acc != 0.0f) atomicAdd(&wsum[cb], acc);
    }
    __syncthreads();
    if (tid < CB && wsum[tid] != 0.0f)
        atomicAdd(&g_B[rb * CB + tid], wsum[tid]);

    // ---- last CTA finishes ----
    __threadfence();
    __syncthreads();
    if (tid == 0) s_rank = atomicAdd(&g_ctr, 1u);
    __syncthreads();
    if (s_rank != GRIDT - 1) return;

    for (int cell = tid; cell < RB * CB; cell += 256) {
        const int crb = cell >> 6;
        const int ccb = cell & 63;
        const float s      = g_B[cell];
        const float rcount = (float)(g_rcum[crb + 1] - g_rcum[crb]);
        const float ccount = (float)(scum[ccb + 1] - scum[ccb]);
        const float x      = s / (rcount * ccount);

        float h1[3], h2[3];
#pragma unroll
        for (int k = 0; k < 3; k++) h1[k] = fmaxf(x * W1[k] + b1[k], 0.0f);
#pragma unroll
        for (int j = 0; j < 3; j++) {
            float z = b2[j];
#pragma unroll
            for (int k = 0; k < 3; k++) z += h1[k] * W2[k * 3 + j];
            h2[j] = fmaxf(z, 0.0f);
        }
        float z = b3[0];
#pragma unroll
        for (int j = 0; j < 3; j++) z += h2[j] * W3[j];

        out[cell]   = 1.0f / (1.0f + expf(-z));
        g_B[cell] = 0.0f;                  // restore invariant
    }

    if (out_size >= RB * CB + 2 * (RB + 1) && tid <= RB) {
        out[RB * CB + tid]            = (float)g_rcum[tid];
        out[RB * CB + (RB + 1) + tid] = (float)scum[tid];
    }
    __syncthreads();
    if (tid == 0) g_ctr = 0;               // reset for next replay
}

// ---------------------------------------------------------------------------
extern "C" void kernel_launch(void* const* d_in, const int* in_sizes, int n_in,
                              void* d_out, int out_size) {
    const float* X       = (const float*)d_in[0];
    const int*   row_ids = (const int*)d_in[1];
    const int*   col_ids = (const int*)d_in[2];
    const float* W1      = (const float*)d_in[3];
    const float* b1      = (const float*)d_in[4];
    const float* W2      = (const float*)d_in[5];
    const float* b2      = (const float*)d_in[6];
    const float* W3      = (const float*)d_in[7];
    const float* b3      = (const float*)d_in[8];
    float* out = (float*)d_out;

    k_main<<<NWORK + 2, 256>>>(X, row_ids, col_ids);
    k_tail<<<GRIDT, 256>>>(W1, b1, W2, b2, W3, b3, out, out_size);
}